// round 1
// baseline (speedup 1.0000x reference)
#include <cuda_runtime.h>

#define BB   2048
#define INN  256
#define HH   128
#define RANKN 8
#define PSPLIT 4

// ---------------- scratch (device globals; no allocs allowed) ----------------
__device__ float g_Z [BB*HH];
__device__ float g_Zi[BB*HH];
__device__ float g_Y [BB*HH];
__device__ float g_R2[BB*HH];
__device__ float g_Tpart[PSPLIT][BB*HH];

// ---------------- generic GEMM + bias + relu (+ optional addon+relu) --------
// out[b,c] = relu(acc + bias[c]); if addon: out = relu(relu(acc+bias)+addon[b,c])
// X: (2048, K) row-major, W: (K, 128) row-major.
__global__ __launch_bounds__(256) void gemm_relu_kernel(
    const float* __restrict__ X, const float* __restrict__ W,
    const float* __restrict__ bias, const float* __restrict__ addon,
    float* __restrict__ out, int K)
{
    __shared__ float sXt[32*32];    // transposed X chunk [k][b]
    __shared__ float sW [32*128];   // W chunk [k][c]
    const int t  = threadIdx.x;
    const int tx = t & 31;          // col group
    const int ty = t >> 5;          // row group
    const int b0 = blockIdx.x * 32;

    float C[4][4] = {};

    for (int k0 = 0; k0 < K; k0 += 32) {
        // load X chunk (32 rows x 32 k) transposed
        {
            int b  = t >> 3;
            int kq = t & 7;
            float4 v = *(const float4*)&X[(b0 + b) * K + k0 + kq * 4];
            sXt[(kq*4+0)*32 + b] = v.x;
            sXt[(kq*4+1)*32 + b] = v.y;
            sXt[(kq*4+2)*32 + b] = v.z;
            sXt[(kq*4+3)*32 + b] = v.w;
        }
        // load W chunk (32 k x 128 c)
        #pragma unroll
        for (int w = 0; w < 4; w++) {
            int idx4 = t + 256 * w;
            int kk = idx4 >> 5, c4 = idx4 & 31;
            *(float4*)&sW[kk*128 + c4*4] = *(const float4*)&W[(k0 + kk) * 128 + c4 * 4];
        }
        __syncthreads();
        #pragma unroll
        for (int kk = 0; kk < 32; kk++) {
            float4 a4 = *(const float4*)&sXt[kk*32 + ty*4];
            float4 w4 = *(const float4*)&sW [kk*128 + tx*4];
            float av[4] = {a4.x, a4.y, a4.z, a4.w};
            float wv[4] = {w4.x, w4.y, w4.z, w4.w};
            #pragma unroll
            for (int i = 0; i < 4; i++)
                #pragma unroll
                for (int j = 0; j < 4; j++)
                    C[i][j] += av[i] * wv[j];
        }
        __syncthreads();
    }

    const int c = tx * 4;
    float bv[4];
    #pragma unroll
    for (int j = 0; j < 4; j++) bv[j] = bias[c + j];

    #pragma unroll
    for (int i = 0; i < 4; i++) {
        int b = b0 + ty * 4 + i;
        float r[4];
        #pragma unroll
        for (int j = 0; j < 4; j++) {
            float v = C[i][j] + bv[j];
            v = v > 0.f ? v : 0.f;
            if (addon) {
                v = v + addon[b * 128 + c + j];
                v = v > 0.f ? v : 0.f;
            }
            r[j] = v;
        }
        float4 o = make_float4(r[0], r[1], r[2], r[3]);
        *(float4*)&out[b * 128 + c] = o;
    }
}

// ---------------- zero Y ------------------------------------------------------
__global__ void zero_y_kernel() {
    int i = blockIdx.x * blockDim.x + threadIdx.x;
    if (i < BB * HH) g_Y[i] = 0.f;
}

// ---------------- quadratic kernel -------------------------------------------
// Tpart[split][b,k] = sum_{p in split} Zi[b,p] * sum_q Z[b,q] * P[p,q,k]
// grid (32, PSPLIT), 128 threads. CTA: 64 b-rows x 128 k, thread tile 8x8.
__global__ __launch_bounds__(128) void quad_kernel(
    const float* __restrict__ Zi, const float* __restrict__ Z,
    const float* __restrict__ Pr /* rank base: [p][q][k] */)
{
    __shared__ float sZt[128*64];   // Z tile transposed [q][b]  (32KB)
    __shared__ float sP [16*128];   // P chunk [q16][k]          (8KB)

    const int t  = threadIdx.x;
    const int tx = t & 15;          // k group
    const int ty = t >> 4;          // b group
    const int b0 = blockIdx.x * 64;
    const int p0 = blockIdx.y * (HH / PSPLIT);

    // stage Z tile transposed
    for (int idx = t; idx < 64 * 128; idx += 128) {
        int b = idx >> 7, q = idx & 127;
        sZt[q * 64 + b] = Z[(b0 + b) * HH + q];
    }
    __syncthreads();

    float C[8][8] = {};

    for (int p = p0; p < p0 + HH / PSPLIT; p++) {
        const float* pb = Pr + p * (HH * HH);

        float zi[8];
        #pragma unroll
        for (int i = 0; i < 8; i++) {
            int r = ty * 4 + (i & 3) + (i >> 2) * 32;
            zi[i] = Zi[(b0 + r) * HH + p];
        }

        float D[8][8] = {};

        // prefetch chunk 0 (16 q rows = 2048 floats)
        float4 R[4];
        #pragma unroll
        for (int w = 0; w < 4; w++)
            R[w] = *(const float4*)(pb + t * 4 + w * 512);

        for (int qc = 0; qc < 8; qc++) {
            __syncthreads();   // prev compute done -> safe to overwrite sP
            #pragma unroll
            for (int w = 0; w < 4; w++)
                *(float4*)&sP[t * 4 + w * 512] = R[w];
            float4 Rn[4];
            if (qc < 7) {
                const float* nb = pb + (qc + 1) * 2048;
                #pragma unroll
                for (int w = 0; w < 4; w++)
                    Rn[w] = *(const float4*)(nb + t * 4 + w * 512);
            }
            __syncthreads();   // sP visible

            #pragma unroll
            for (int q = 0; q < 16; q++) {
                int qq = qc * 16 + q;
                float4 za = *(const float4*)&sZt[qq * 64 + ty * 4];
                float4 zb = *(const float4*)&sZt[qq * 64 + 32 + ty * 4];
                float4 wa = *(const float4*)&sP [q * 128 + tx * 4];
                float4 wb = *(const float4*)&sP [q * 128 + 64 + tx * 4];
                float zv[8] = {za.x, za.y, za.z, za.w, zb.x, zb.y, zb.z, zb.w};
                float wv[8] = {wa.x, wa.y, wa.z, wa.w, wb.x, wb.y, wb.z, wb.w};
                #pragma unroll
                for (int i = 0; i < 8; i++)
                    #pragma unroll
                    for (int j = 0; j < 8; j++)
                        D[i][j] += zv[i] * wv[j];
            }
            #pragma unroll
            for (int w = 0; w < 4; w++) R[w] = Rn[w];
        }

        #pragma unroll
        for (int i = 0; i < 8; i++)
            #pragma unroll
            for (int j = 0; j < 8; j++)
                C[i][j] += zi[i] * D[i][j];
    }

    float* To = &g_Tpart[blockIdx.y][0];
    #pragma unroll
    for (int i = 0; i < 8; i++) {
        int r = b0 + ty * 4 + (i & 3) + (i >> 2) * 32;
        *(float4*)&To[r * HH + tx * 4]      = make_float4(C[i][0], C[i][1], C[i][2], C[i][3]);
        *(float4*)&To[r * HH + 64 + tx * 4] = make_float4(C[i][4], C[i][5], C[i][6], C[i][7]);
    }
}

// ---------------- BatchNorm over rank output + Y accumulate ------------------
// one block per column k; sums the PSPLIT partials, two-pass batch stats.
__global__ __launch_bounds__(256) void bn_rank_kernel(
    const float* __restrict__ g, const float* __restrict__ bet)
{
    __shared__ float red[256];
    const int k = blockIdx.x;
    const int t = threadIdx.x;

    float xv[8];
    float s = 0.f;
    #pragma unroll
    for (int j = 0; j < 8; j++) {
        int b = j * 256 + t;
        float x = g_Tpart[0][b*HH + k] + g_Tpart[1][b*HH + k]
                + g_Tpart[2][b*HH + k] + g_Tpart[3][b*HH + k];
        xv[j] = x;
        s += x;
    }
    red[t] = s; __syncthreads();
    for (int o = 128; o > 0; o >>= 1) { if (t < o) red[t] += red[t + o]; __syncthreads(); }
    float mean = red[0] * (1.f / BB);
    __syncthreads();

    float s2 = 0.f;
    #pragma unroll
    for (int j = 0; j < 8; j++) { float d = xv[j] - mean; s2 += d * d; }
    red[t] = s2; __syncthreads();
    for (int o = 128; o > 0; o >>= 1) { if (t < o) red[t] += red[t + o]; __syncthreads(); }
    float var = red[0] * (1.f / BB);

    float inv = rsqrtf(var + 1e-5f);
    float gk = g[k], bk = bet[k];
    #pragma unroll
    for (int j = 0; j < 8; j++) {
        int b = j * 256 + t;
        float z = (xv[j] - mean) * inv * gk + bk;
        g_Zi[b*HH + k] = z;
        g_Y [b*HH + k] += z * (1.f / RANKN);
    }
}

// ---------------- BatchNorm on Y (in place) ----------------------------------
__global__ __launch_bounds__(256) void bn_final_kernel(
    const float* __restrict__ g, const float* __restrict__ bet)
{
    __shared__ float red[256];
    const int k = blockIdx.x;
    const int t = threadIdx.x;

    float xv[8];
    float s = 0.f;
    #pragma unroll
    for (int j = 0; j < 8; j++) {
        int b = j * 256 + t;
        float x = g_Y[b*HH + k];
        xv[j] = x;
        s += x;
    }
    red[t] = s; __syncthreads();
    for (int o = 128; o > 0; o >>= 1) { if (t < o) red[t] += red[t + o]; __syncthreads(); }
    float mean = red[0] * (1.f / BB);
    __syncthreads();

    float s2 = 0.f;
    #pragma unroll
    for (int j = 0; j < 8; j++) { float d = xv[j] - mean; s2 += d * d; }
    red[t] = s2; __syncthreads();
    for (int o = 128; o > 0; o >>= 1) { if (t < o) red[t] += red[t + o]; __syncthreads(); }
    float var = red[0] * (1.f / BB);

    float inv = rsqrtf(var + 1e-5f);
    float gk = g[k], bk = bet[k];
    #pragma unroll
    for (int j = 0; j < 8; j++) {
        int b = j * 256 + t;
        g_Y[b*HH + k] = (xv[j] - mean) * inv * gk + bk;
    }
}

// ---------------- launch ------------------------------------------------------
extern "C" void kernel_launch(void* const* d_in, const int* in_sizes, int n_in,
                              void* d_out, int out_size)
{
    const float* X  = (const float*)d_in[0];
    const float* W1 = (const float*)d_in[1];
    const float* b1 = (const float*)d_in[2];
    const float* W2 = (const float*)d_in[3];
    const float* b2 = (const float*)d_in[4];
    const float* W3 = (const float*)d_in[5];
    const float* b3 = (const float*)d_in[6];
    const float* P  = (const float*)d_in[7];
    const float* gz = (const float*)d_in[8];
    const float* bz = (const float*)d_in[9];
    const float* gy = (const float*)d_in[10];
    const float* by = (const float*)d_in[11];
    float* out = (float*)d_out;

    float *Zp, *Zip, *Yp, *R2p;
    cudaGetSymbolAddress((void**)&Zp,  g_Z);
    cudaGetSymbolAddress((void**)&Zip, g_Zi);
    cudaGetSymbolAddress((void**)&Yp,  g_Y);
    cudaGetSymbolAddress((void**)&R2p, g_R2);

    // Z = relu(X@W1 + b1), R2 = relu(X@W2 + b2)
    gemm_relu_kernel<<<64, 256>>>(X, W1, b1, nullptr, Zp,  INN);
    gemm_relu_kernel<<<64, 256>>>(X, W2, b2, nullptr, R2p, INN);
    zero_y_kernel<<<(BB*HH + 255)/256, 256>>>();

    for (int r = 0; r < RANKN; r++) {
        const float* Pr = P + (size_t)r * HH * HH * HH;
        const float* ZiIn = (r == 0) ? Zp : Zip;
        quad_kernel<<<dim3(BB/64, PSPLIT), 128>>>(ZiIn, Zp, Pr);
        bn_rank_kernel<<<HH, 256>>>(gz, bz);
    }

    bn_final_kernel<<<HH, 256>>>(gy, by);

    // out = relu(relu(Y@W3 + b3) + R2)
    gemm_relu_kernel<<<64, 256>>>(Yp, W3, b3, R2p, out, HH);
}

// round 7
// speedup vs baseline: 1.1485x; 1.1485x over previous
#include <cuda_runtime.h>
#include <cuda_bf16.h>
#include <cstdint>

#define BB   2048
#define INN  256
#define HH   128
#define RANKN 8
#define CHUNKS 32
#define PPC   4          // p-values per chunk (CHUNKS*PPC = 128)

// ---------------- scratch (device globals) -----------------------------------
__device__ float g_Z [BB*HH];
__device__ float g_Zi[BB*HH];
__device__ float g_Y [BB*HH];
__device__ float g_R2[BB*HH];
__device__ __nv_bfloat16 g_Pth[(size_t)RANKN*HH*HH*HH];   // [r][p][k][q] hi
__device__ __nv_bfloat16 g_Ptl[(size_t)RANKN*HH*HH*HH];   // [r][p][k][q] lo
__device__ float g_part[CHUNKS][BB*HH];                   // 33.5 MB partials

// ---------------- warp-mma helpers -------------------------------------------
__device__ __forceinline__ void ldsm_x4(uint32_t& r0, uint32_t& r1, uint32_t& r2,
                                        uint32_t& r3, const void* p) {
    uint32_t a;
    asm("{ .reg .u64 t; cvta.to.shared.u64 t, %1; cvt.u32.u64 %0, t; }" : "=r"(a) : "l"(p));
    asm volatile("ldmatrix.sync.aligned.m8n8.x4.shared.b16 {%0,%1,%2,%3}, [%4];"
                 : "=r"(r0), "=r"(r1), "=r"(r2), "=r"(r3) : "r"(a));
}
__device__ __forceinline__ void mma_bf16(float* c, const uint32_t* a, const uint32_t* b) {
    asm volatile("mma.sync.aligned.m16n8k16.row.col.f32.bf16.bf16.f32 "
                 "{%0,%1,%2,%3}, {%4,%5,%6,%7}, {%8,%9}, {%0,%1,%2,%3};"
                 : "+f"(c[0]), "+f"(c[1]), "+f"(c[2]), "+f"(c[3])
                 : "r"(a[0]), "r"(a[1]), "r"(a[2]), "r"(a[3]), "r"(b[0]), "r"(b[1]));
}

// ---------------- P pre-split + transpose ------------------------------------
// out[r][p][k][q] (hi/lo bf16) from P[r][p][q][k] fp32
__global__ __launch_bounds__(256) void prep_P_kernel(const float* __restrict__ P) {
    __shared__ float tile[128 * 129];
    const int t  = threadIdx.x;
    const int rp = blockIdx.x;
    const float* src = P + (size_t)rp * 16384;
    for (int i = 0; i < 64; i++) {
        int idx = t + i * 256;                 // q*128 + k
        tile[(idx >> 7) * 129 + (idx & 127)] = src[idx];
    }
    __syncthreads();
    __nv_bfloat162* dh = (__nv_bfloat162*)(g_Pth + (size_t)rp * 16384);
    __nv_bfloat162* dl = (__nv_bfloat162*)(g_Ptl + (size_t)rp * 16384);
    for (int i = 0; i < 32; i++) {
        int pi = t + i * 256;
        int o = pi * 2;
        int k = o >> 7, q = o & 127;
        float v0 = tile[q * 129 + k];
        float v1 = tile[(q + 1) * 129 + k];
        __nv_bfloat16 h0 = __float2bfloat16_rn(v0);
        __nv_bfloat16 h1 = __float2bfloat16_rn(v1);
        __nv_bfloat16 l0 = __float2bfloat16_rn(v0 - __bfloat162float(h0));
        __nv_bfloat16 l1 = __float2bfloat16_rn(v1 - __bfloat162float(h1));
        dh[pi] = __halves2bfloat162(h0, h1);
        dl[pi] = __halves2bfloat162(l0, l1);
    }
}

// ---------------- GEMM + bias + relu (+ optional addon+relu) -----------------
__global__ __launch_bounds__(256) void gemm_relu_kernel(
    const float* __restrict__ X, const float* __restrict__ W,
    const float* __restrict__ bias, const float* __restrict__ addon,
    float* __restrict__ out, int K)
{
    __shared__ float sXt[32*32];
    __shared__ float sW [32*128];
    const int t  = threadIdx.x;
    const int tx = t & 31;
    const int ty = t >> 5;
    const int b0 = blockIdx.x * 32;

    float C[4][4] = {};
    for (int k0 = 0; k0 < K; k0 += 32) {
        {
            int b  = t >> 3;
            int kq = t & 7;
            float4 v = *(const float4*)&X[(b0 + b) * K + k0 + kq * 4];
            sXt[(kq*4+0)*32 + b] = v.x;
            sXt[(kq*4+1)*32 + b] = v.y;
            sXt[(kq*4+2)*32 + b] = v.z;
            sXt[(kq*4+3)*32 + b] = v.w;
        }
        #pragma unroll
        for (int w = 0; w < 4; w++) {
            int idx4 = t + 256 * w;
            int kk = idx4 >> 5, c4 = idx4 & 31;
            *(float4*)&sW[kk*128 + c4*4] = *(const float4*)&W[(k0 + kk) * 128 + c4 * 4];
        }
        __syncthreads();
        #pragma unroll
        for (int kk = 0; kk < 32; kk++) {
            float4 a4 = *(const float4*)&sXt[kk*32 + ty*4];
            float4 w4 = *(const float4*)&sW [kk*128 + tx*4];
            float av[4] = {a4.x, a4.y, a4.z, a4.w};
            float wv[4] = {w4.x, w4.y, w4.z, w4.w};
            #pragma unroll
            for (int i = 0; i < 4; i++)
                #pragma unroll
                for (int j = 0; j < 4; j++)
                    C[i][j] += av[i] * wv[j];
        }
        __syncthreads();
    }

    const int c = tx * 4;
    float bv[4];
    #pragma unroll
    for (int j = 0; j < 4; j++) bv[j] = bias[c + j];

    #pragma unroll
    for (int i = 0; i < 4; i++) {
        int b = b0 + ty * 4 + i;
        float r[4];
        #pragma unroll
        for (int j = 0; j < 4; j++) {
            float v = C[i][j] + bv[j];
            v = v > 0.f ? v : 0.f;
            if (addon) {
                v = v + addon[b * 128 + c + j];
                v = v > 0.f ? v : 0.f;
            }
            r[j] = v;
        }
        *(float4*)&out[b * 128 + c] = make_float4(r[0], r[1], r[2], r[3]);
    }
}

// ---------------- quadratic rank kernel (warp mma, split-3 bf16) -------------
// partial[chunk][b,k] = sum_{p in chunk} Zi[b,p] * sum_q Z[b,q] * P[r,p,q,k]
// grid (16 M-tiles, 32 chunks), 256 threads = 8 warps (32x64 each).
// A'[b,q] = Zi[b,p]*Z[b,q] staged fp32->bf16 hi/lo in smem; B = Pt[r][p] hi/lo.
#define LDA 136                        // padded bf16 row stride
#define SM_AH 0
#define SM_AL (128*LDA*2)
#define SM_BH (2*128*LDA*2)
#define SM_BL (3*128*LDA*2)
#define SM_QTOT (4*128*LDA*2)          // 139264 B

__global__ __launch_bounds__(256) void quad_mma_kernel(
    const float* __restrict__ zi_in, int r)
{
    extern __shared__ char smem[];
    __nv_bfloat16* sAh = (__nv_bfloat16*)(smem + SM_AH);
    __nv_bfloat16* sAl = (__nv_bfloat16*)(smem + SM_AL);
    __nv_bfloat16* sBh = (__nv_bfloat16*)(smem + SM_BH);
    __nv_bfloat16* sBl = (__nv_bfloat16*)(smem + SM_BL);

    const int t    = threadIdx.x;
    const int w    = t >> 5;
    const int lane = t & 31;
    const int m0   = blockIdx.x * 128;
    const int chunk= blockIdx.y;
    const int wm   = (w >> 1) * 32;
    const int wn   = (w & 1) * 64;

    // ldmatrix per-lane row/col pattern (same for A and B x4 tiles)
    const int lrow  = ((lane >> 3) & 1) * 8 + (lane & 7);
    const int lcol8 = ((lane >> 4) & 1) * 8;

    // staging assignment: thread covers row (t>>1), q-half (t&1)*64
    const int srow = t >> 1;
    const int sq0  = (t & 1) * 64;

    float acc[2][8][4] = {};

    for (int pi = 0; pi < PPC; pi++) {
        const int p = chunk * PPC + pi;
        __syncthreads();   // previous iteration's smem reads done

        // ---- stage A' hi/lo
        {
            float ziv = zi_in[(m0 + srow) * HH + p];
            const float2* zrow = (const float2*)(g_Z + (size_t)(m0 + srow) * HH + sq0);
            __nv_bfloat162* ah = (__nv_bfloat162*)(sAh + srow * LDA + sq0);
            __nv_bfloat162* al = (__nv_bfloat162*)(sAl + srow * LDA + sq0);
            #pragma unroll
            for (int j = 0; j < 32; j++) {
                float2 z = zrow[j];
                float v0 = ziv * z.x, v1 = ziv * z.y;
                __nv_bfloat16 h0 = __float2bfloat16_rn(v0);
                __nv_bfloat16 h1 = __float2bfloat16_rn(v1);
                __nv_bfloat16 l0 = __float2bfloat16_rn(v0 - __bfloat162float(h0));
                __nv_bfloat16 l1 = __float2bfloat16_rn(v1 - __bfloat162float(h1));
                ah[j] = __halves2bfloat162(h0, h1);
                al[j] = __halves2bfloat162(l0, l1);
            }
        }

        // ---- stage B (Pt[r][p], [k][q] 128x128 bf16) hi/lo
        {
            const size_t tile = ((size_t)r * HH + p) * 16384;
            const uint4* srcH = (const uint4*)(g_Pth + tile);
            const uint4* srcL = (const uint4*)(g_Ptl + tile);
            #pragma unroll
            for (int pass = 0; pass < 8; pass++) {
                int idx = t + pass * 256;      // 16B chunk id, 16 per row
                int row = idx >> 4, qc = idx & 15;
                *(uint4*)(sBh + row * LDA + qc * 8) = srcH[idx];
                *(uint4*)(sBl + row * LDA + qc * 8) = srcL[idx];
            }
        }
        __syncthreads();

        // ---- mma over q
        #pragma unroll
        for (int ks = 0; ks < 8; ks++) {
            const int kq = ks * 16;
            uint32_t ah[2][4], al[2][4], bh[8][2], bl[8][2];
            #pragma unroll
            for (int mt = 0; mt < 2; mt++) {
                const __nv_bfloat16* pa = sAh + (wm + mt*16 + lrow) * LDA + kq + lcol8;
                ldsm_x4(ah[mt][0], ah[mt][1], ah[mt][2], ah[mt][3], pa);
                const __nv_bfloat16* pl = sAl + (wm + mt*16 + lrow) * LDA + kq + lcol8;
                ldsm_x4(al[mt][0], al[mt][1], al[mt][2], al[mt][3], pl);
            }
            #pragma unroll
            for (int g = 0; g < 4; g++) {
                uint32_t r0, r1, r2, r3;
                const __nv_bfloat16* pb = sBh + (wn + g*16 + lrow) * LDA + kq + lcol8;
                ldsm_x4(r0, r1, r2, r3, pb);
                bh[g*2][0] = r0; bh[g*2+1][0] = r1; bh[g*2][1] = r2; bh[g*2+1][1] = r3;
                const __nv_bfloat16* pc = sBl + (wn + g*16 + lrow) * LDA + kq + lcol8;
                ldsm_x4(r0, r1, r2, r3, pc);
                bl[g*2][0] = r0; bl[g*2+1][0] = r1; bl[g*2][1] = r2; bl[g*2+1][1] = r3;
            }
            #pragma unroll
            for (int mt = 0; mt < 2; mt++)
                #pragma unroll
                for (int nt = 0; nt < 8; nt++) {
                    mma_bf16(acc[mt][nt], ah[mt], bh[nt]);
                    mma_bf16(acc[mt][nt], al[mt], bh[nt]);
                    mma_bf16(acc[mt][nt], ah[mt], bl[nt]);
                }
        }
    }

    // ---- write partial tile
    float* dst = &g_part[chunk][0];
    #pragma unroll
    for (int mt = 0; mt < 2; mt++) {
        int row0 = m0 + wm + mt * 16 + (lane >> 2);
        #pragma unroll
        for (int nt = 0; nt < 8; nt++) {
            int col = wn + nt * 8 + (lane & 3) * 2;
            *(float2*)&dst[(size_t)row0 * HH + col] =
                make_float2(acc[mt][nt][0], acc[mt][nt][1]);
            *(float2*)&dst[(size_t)(row0 + 8) * HH + col] =
                make_float2(acc[mt][nt][2], acc[mt][nt][3]);
        }
    }
}

// ---------------- zero Y ------------------------------------------------------
__global__ void zero_y_kernel() {
    int i = blockIdx.x * blockDim.x + threadIdx.x;
    if (i < BB * HH) g_Y[i] = 0.f;
}

// ---------------- combine partials + BatchNorm + Y accumulate ----------------
__global__ __launch_bounds__(256) void bn_rank_kernel(
    const float* __restrict__ g, const float* __restrict__ bet)
{
    __shared__ float red[256];
    const int k = blockIdx.x;
    const int t = threadIdx.x;

    float xv[8];
    float s = 0.f;
    #pragma unroll
    for (int j = 0; j < 8; j++) {
        int b = j * 256 + t;
        float x = 0.f;
        #pragma unroll
        for (int c = 0; c < CHUNKS; c++)
            x += g_part[c][b*HH + k];
        xv[j] = x;
        s += x;
    }
    red[t] = s; __syncthreads();
    for (int o = 128; o > 0; o >>= 1) { if (t < o) red[t] += red[t + o]; __syncthreads(); }
    float mean = red[0] * (1.f / BB);
    __syncthreads();

    float s2 = 0.f;
    #pragma unroll
    for (int j = 0; j < 8; j++) { float d = xv[j] - mean; s2 += d * d; }
    red[t] = s2; __syncthreads();
    for (int o = 128; o > 0; o >>= 1) { if (t < o) red[t] += red[t + o]; __syncthreads(); }
    float var = red[0] * (1.f / BB);

    float inv = rsqrtf(var + 1e-5f);
    float gk = g[k], bk = bet[k];
    #pragma unroll
    for (int j = 0; j < 8; j++) {
        int b = j * 256 + t;
        float z = (xv[j] - mean) * inv * gk + bk;
        g_Zi[b*HH + k] = z;
        g_Y [b*HH + k] += z * (1.f / RANKN);
    }
}

// ---------------- BatchNorm on Y (in place) ----------------------------------
__global__ __launch_bounds__(256) void bn_final_kernel(
    const float* __restrict__ g, const float* __restrict__ bet)
{
    __shared__ float red[256];
    const int k = blockIdx.x;
    const int t = threadIdx.x;

    float xv[8];
    float s = 0.f;
    #pragma unroll
    for (int j = 0; j < 8; j++) {
        int b = j * 256 + t;
        float x = g_Y[b*HH + k];
        xv[j] = x;
        s += x;
    }
    red[t] = s; __syncthreads();
    for (int o = 128; o > 0; o >>= 1) { if (t < o) red[t] += red[t + o]; __syncthreads(); }
    float mean = red[0] * (1.f / BB);
    __syncthreads();

    float s2 = 0.f;
    #pragma unroll
    for (int j = 0; j < 8; j++) { float d = xv[j] - mean; s2 += d * d; }
    red[t] = s2; __syncthreads();
    for (int o = 128; o > 0; o >>= 1) { if (t < o) red[t] += red[t + o]; __syncthreads(); }
    float var = red[0] * (1.f / BB);

    float inv = rsqrtf(var + 1e-5f);
    float gk = g[k], bk = bet[k];
    #pragma unroll
    for (int j = 0; j < 8; j++) {
        int b = j * 256 + t;
        g_Y[b*HH + k] = (xv[j] - mean) * inv * gk + bk;
    }
}

// ---------------- launch ------------------------------------------------------
extern "C" void kernel_launch(void* const* d_in, const int* in_sizes, int n_in,
                              void* d_out, int out_size)
{
    const float* X  = (const float*)d_in[0];
    const float* W1 = (const float*)d_in[1];
    const float* b1 = (const float*)d_in[2];
    const float* W2 = (const float*)d_in[3];
    const float* b2 = (const float*)d_in[4];
    const float* W3 = (const float*)d_in[5];
    const float* b3 = (const float*)d_in[6];
    const float* P  = (const float*)d_in[7];
    const float* gz = (const float*)d_in[8];
    const float* bz = (const float*)d_in[9];
    const float* gy = (const float*)d_in[10];
    const float* by = (const float*)d_in[11];
    float* out = (float*)d_out;

    float *Zp, *Zip, *Yp, *R2p;
    cudaGetSymbolAddress((void**)&Zp,  g_Z);
    cudaGetSymbolAddress((void**)&Zip, g_Zi);
    cudaGetSymbolAddress((void**)&Yp,  g_Y);
    cudaGetSymbolAddress((void**)&R2p, g_R2);

    cudaFuncSetAttribute(quad_mma_kernel, cudaFuncAttributeMaxDynamicSharedMemorySize, SM_QTOT);

    // P pre-split + transpose (independent of everything else)
    prep_P_kernel<<<RANKN * HH, 256>>>(P);

    // Z = relu(X@W1 + b1); R2 = relu(X@W2 + b2)
    gemm_relu_kernel<<<64, 256>>>(X, W1, b1, nullptr, Zp,  INN);
    gemm_relu_kernel<<<64, 256>>>(X, W2, b2, nullptr, R2p, INN);
    zero_y_kernel<<<(BB*HH + 255)/256, 256>>>();

    // serial recurrence: tensor-core quad (parallel within rank) + BN per rank
    for (int r = 0; r < RANKN; r++) {
        const float* ziIn = (r == 0) ? Zp : Zip;
        quad_mma_kernel<<<dim3(BB/128, CHUNKS), 256, SM_QTOT>>>(ziIn, r);
        bn_rank_kernel<<<HH, 256>>>(gz, bz);
    }

    bn_final_kernel<<<HH, 256>>>(gy, by);

    // out = relu(relu(Y@W3 + b3) + R2)
    gemm_relu_kernel<<<64, 256>>>(Yp, W3, b3, R2p, out, HH);
}

// round 11
// speedup vs baseline: 2.2272x; 1.9392x over previous
#include <cuda_runtime.h>
#include <cuda_bf16.h>
#include <cstdint>

#define BB   2048
#define INN  256
#define HH   128
#define RANKN 8
#define CHUNKS 8
#define PPC   16         // p-values per chunk (CHUNKS*PPC = 128)

// ---------------- scratch (device globals) -----------------------------------
__device__ float g_Z [BB*HH];
__device__ float g_Zi[BB*HH];
__device__ float g_Y [BB*HH];
__device__ float g_R2[BB*HH];
__device__ __nv_bfloat16 g_Zh[BB*HH];
__device__ __nv_bfloat16 g_Zl[BB*HH];
__device__ __nv_bfloat16 g_Pth[(size_t)RANKN*HH*HH*HH];   // [r][p][k][q] hi
__device__ __nv_bfloat16 g_Ptl[(size_t)RANKN*HH*HH*HH];   // [r][p][k][q] lo
__device__ float g_part[CHUNKS][BB*HH];                   // 8.4 MB partials

// ---------------- helpers -----------------------------------------------------
__device__ __forceinline__ uint32_t smem_u32(const void* p) {
    uint32_t a;
    asm("{ .reg .u64 t; cvta.to.shared.u64 t, %1; cvt.u32.u64 %0, t; }" : "=r"(a) : "l"(p));
    return a;
}
__device__ __forceinline__ void ldsm_x4(uint32_t& r0, uint32_t& r1, uint32_t& r2,
                                        uint32_t& r3, const void* p) {
    uint32_t a = smem_u32(p);
    asm volatile("ldmatrix.sync.aligned.m8n8.x4.shared.b16 {%0,%1,%2,%3}, [%4];"
                 : "=r"(r0), "=r"(r1), "=r"(r2), "=r"(r3) : "r"(a));
}
__device__ __forceinline__ void mma_bf16(float* c, const uint32_t* a, const uint32_t* b) {
    asm volatile("mma.sync.aligned.m16n8k16.row.col.f32.bf16.bf16.f32 "
                 "{%0,%1,%2,%3}, {%4,%5,%6,%7}, {%8,%9}, {%0,%1,%2,%3};"
                 : "+f"(c[0]), "+f"(c[1]), "+f"(c[2]), "+f"(c[3])
                 : "r"(a[0]), "r"(a[1]), "r"(a[2]), "r"(a[3]), "r"(b[0]), "r"(b[1]));
}
__device__ __forceinline__ void cp16(uint32_t saddr, const void* g) {
    asm volatile("cp.async.cg.shared.global [%0], [%1], 16;" :: "r"(saddr), "l"(g));
}
__device__ __forceinline__ void cp_commit() { asm volatile("cp.async.commit_group;"); }
template<int N> __device__ __forceinline__ void cp_wait() {
    asm volatile("cp.async.wait_group %0;" :: "n"(N));
}

// ---------------- P pre-split + transpose ------------------------------------
// out[r][p][k][q] (hi/lo bf16) from P[r][p][q][k] fp32
__global__ __launch_bounds__(256) void prep_P_kernel(const float* __restrict__ P) {
    __shared__ float tile[128 * 129];
    const int t  = threadIdx.x;
    const int rp = blockIdx.x;
    const float* src = P + (size_t)rp * 16384;
    for (int i = 0; i < 64; i++) {
        int idx = t + i * 256;                 // q*128 + k
        tile[(idx >> 7) * 129 + (idx & 127)] = src[idx];
    }
    __syncthreads();
    __nv_bfloat162* dh = (__nv_bfloat162*)(g_Pth + (size_t)rp * 16384);
    __nv_bfloat162* dl = (__nv_bfloat162*)(g_Ptl + (size_t)rp * 16384);
    for (int i = 0; i < 32; i++) {
        int pi = t + i * 256;
        int o = pi * 2;
        int k = o >> 7, q = o & 127;
        float v0 = tile[q * 129 + k];
        float v1 = tile[(q + 1) * 129 + k];
        __nv_bfloat16 h0 = __float2bfloat16_rn(v0);
        __nv_bfloat16 h1 = __float2bfloat16_rn(v1);
        __nv_bfloat16 l0 = __float2bfloat16_rn(v0 - __bfloat162float(h0));
        __nv_bfloat16 l1 = __float2bfloat16_rn(v1 - __bfloat162float(h1));
        dh[pi] = __halves2bfloat162(h0, h1);
        dl[pi] = __halves2bfloat162(l0, l1);
    }
}

// ---------------- GEMM + bias + relu (+ optional addon, + optional split) ----
__global__ __launch_bounds__(256) void gemm_relu_kernel(
    const float* __restrict__ X, const float* __restrict__ W,
    const float* __restrict__ bias, const float* __restrict__ addon,
    float* __restrict__ out, int K,
    __nv_bfloat16* __restrict__ oh, __nv_bfloat16* __restrict__ ol)
{
    __shared__ float sXt[32*32];
    __shared__ float sW [32*128];
    const int t  = threadIdx.x;
    const int tx = t & 31;
    const int ty = t >> 5;
    const int b0 = blockIdx.x * 32;

    float C[4][4] = {};
    for (int k0 = 0; k0 < K; k0 += 32) {
        {
            int b  = t >> 3;
            int kq = t & 7;
            float4 v = *(const float4*)&X[(b0 + b) * K + k0 + kq * 4];
            sXt[(kq*4+0)*32 + b] = v.x;
            sXt[(kq*4+1)*32 + b] = v.y;
            sXt[(kq*4+2)*32 + b] = v.z;
            sXt[(kq*4+3)*32 + b] = v.w;
        }
        #pragma unroll
        for (int w = 0; w < 4; w++) {
            int idx4 = t + 256 * w;
            int kk = idx4 >> 5, c4 = idx4 & 31;
            *(float4*)&sW[kk*128 + c4*4] = *(const float4*)&W[(k0 + kk) * 128 + c4 * 4];
        }
        __syncthreads();
        #pragma unroll
        for (int kk = 0; kk < 32; kk++) {
            float4 a4 = *(const float4*)&sXt[kk*32 + ty*4];
            float4 w4 = *(const float4*)&sW [kk*128 + tx*4];
            float av[4] = {a4.x, a4.y, a4.z, a4.w};
            float wv[4] = {w4.x, w4.y, w4.z, w4.w};
            #pragma unroll
            for (int i = 0; i < 4; i++)
                #pragma unroll
                for (int j = 0; j < 4; j++)
                    C[i][j] += av[i] * wv[j];
        }
        __syncthreads();
    }

    const int c = tx * 4;
    float bv[4];
    #pragma unroll
    for (int j = 0; j < 4; j++) bv[j] = bias[c + j];

    #pragma unroll
    for (int i = 0; i < 4; i++) {
        int b = b0 + ty * 4 + i;
        float r[4];
        #pragma unroll
        for (int j = 0; j < 4; j++) {
            float v = C[i][j] + bv[j];
            v = v > 0.f ? v : 0.f;
            if (addon) {
                v = v + addon[b * 128 + c + j];
                v = v > 0.f ? v : 0.f;
            }
            r[j] = v;
        }
        *(float4*)&out[b * 128 + c] = make_float4(r[0], r[1], r[2], r[3]);
        if (oh) {
            __nv_bfloat16 h[4], l[4];
            #pragma unroll
            for (int j = 0; j < 4; j++) {
                h[j] = __float2bfloat16_rn(r[j]);
                l[j] = __float2bfloat16_rn(r[j] - __bfloat162float(h[j]));
            }
            *(__nv_bfloat162*)&oh[b*128 + c]     = __halves2bfloat162(h[0], h[1]);
            *(__nv_bfloat162*)&oh[b*128 + c + 2] = __halves2bfloat162(h[2], h[3]);
            *(__nv_bfloat162*)&ol[b*128 + c]     = __halves2bfloat162(l[0], l[1]);
            *(__nv_bfloat162*)&ol[b*128 + c + 2] = __halves2bfloat162(l[2], l[3]);
        }
    }
}

// ---------------- quadratic rank kernel v2 -----------------------------------
// For each p: D = Z @ P_p (3-product bf16 split, tensor cores), then
// C += zi[b,p] * D (fp32, register epilogue). B double-buffered via cp.async.
// grid (16 M-tiles, 8 chunks), 256 threads = 8 warps (32x64 tiles).
#define LDA    136                      // padded bf16 row stride
#define ABYTES (128*LDA*2)              // 34816 per 128x128 bf16 tile
#define O_AH   0
#define O_AL   ABYTES
#define O_B0   (2*ABYTES)
#define O_B1   (4*ABYTES)
#define O_ZI   (6*ABYTES)               // 208896
#define SM_QTOT (O_ZI + 128*17*4)       // 217600

__global__ __launch_bounds__(256) void quad_mma_kernel(
    const float* __restrict__ zi_in, int r)
{
    extern __shared__ char smem[];
    const uint32_t sb = smem_u32(smem);
    const int t     = threadIdx.x;
    const int w     = t >> 5;
    const int lane  = t & 31;
    const int m0    = blockIdx.x * 128;
    const int chunk = blockIdx.y;
    const int wm    = (w >> 1) * 32;
    const int wn    = (w & 1) * 64;
    const int p0    = chunk * PPC;

    const int lrow  = ((lane >> 3) & 1) * 8 + (lane & 7);
    const int lcol8 = ((lane >> 4) & 1) * 8;

    __nv_bfloat16* sAh = (__nv_bfloat16*)(smem + O_AH);
    __nv_bfloat16* sAl = (__nv_bfloat16*)(smem + O_AL);
    float*         szi = (float*)(smem + O_ZI);
    const uint32_t oB[2] = {O_B0, O_B1};

    // ---- stage A = Z hi/lo tiles (once)
    {
        const char* gh = (const char*)(g_Zh + (size_t)m0 * HH);
        const char* gl = (const char*)(g_Zl + (size_t)m0 * HH);
        #pragma unroll
        for (int pass = 0; pass < 8; pass++) {
            int idx = t + pass * 256;           // 16B unit, 16 per row
            uint32_t off = (uint32_t)(idx >> 4) * (LDA*2) + (uint32_t)(idx & 15) * 16;
            cp16(sb + O_AH + off, gh + (size_t)idx * 16);
            cp16(sb + O_AL + off, gl + (size_t)idx * 16);
        }
    }
    // ---- stage B for p0 into buf0 (same commit group)
    {
        const size_t tile = ((size_t)r * HH + p0) * 16384;
        const char* gh = (const char*)(g_Pth + tile);
        const char* gl = (const char*)(g_Ptl + tile);
        #pragma unroll
        for (int pass = 0; pass < 8; pass++) {
            int idx = t + pass * 256;
            uint32_t off = (uint32_t)(idx >> 4) * (LDA*2) + (uint32_t)(idx & 15) * 16;
            cp16(sb + O_B0 + off,          gh + (size_t)idx * 16);
            cp16(sb + O_B0 + ABYTES + off, gl + (size_t)idx * 16);
        }
    }
    cp_commit();

    // ---- stage zi chunk [128 rows][16 p] (plain loads)
    {
        int row = t >> 1, h = (t & 1) * 8;
        const float* zp = zi_in + (size_t)(m0 + row) * HH + p0 + h;
        float4 v0 = *(const float4*)(zp);
        float4 v1 = *(const float4*)(zp + 4);
        float* d = szi + row * 17 + h;
        d[0]=v0.x; d[1]=v0.y; d[2]=v0.z; d[3]=v0.w;
        d[4]=v1.x; d[5]=v1.y; d[6]=v1.z; d[7]=v1.w;
    }

    float accC[2][8][4] = {};

    for (int pi = 0; pi < PPC; pi++) {
        // prefetch next B, then wait for current
        if (pi + 1 < PPC) {
            const size_t tile = ((size_t)r * HH + p0 + pi + 1) * 16384;
            const char* gh = (const char*)(g_Pth + tile);
            const char* gl = (const char*)(g_Ptl + tile);
            const uint32_t base = sb + oB[(pi + 1) & 1];
            #pragma unroll
            for (int pass = 0; pass < 8; pass++) {
                int idx = t + pass * 256;
                uint32_t off = (uint32_t)(idx >> 4) * (LDA*2) + (uint32_t)(idx & 15) * 16;
                cp16(base + off,          gh + (size_t)idx * 16);
                cp16(base + ABYTES + off, gl + (size_t)idx * 16);
            }
            cp_commit();
            cp_wait<1>();
        } else {
            cp_wait<0>();
        }
        __syncthreads();

        __nv_bfloat16* sBh = (__nv_bfloat16*)(smem + oB[pi & 1]);
        __nv_bfloat16* sBl = (__nv_bfloat16*)(smem + oB[pi & 1] + ABYTES);

        float D[2][8][4] = {};

        #pragma unroll
        for (int ks = 0; ks < 8; ks++) {
            const int kq = ks * 16;
            uint32_t ah[2][4], al[2][4];
            #pragma unroll
            for (int mt = 0; mt < 2; mt++) {
                ldsm_x4(ah[mt][0], ah[mt][1], ah[mt][2], ah[mt][3],
                        sAh + (wm + mt*16 + lrow) * LDA + kq + lcol8);
                ldsm_x4(al[mt][0], al[mt][1], al[mt][2], al[mt][3],
                        sAl + (wm + mt*16 + lrow) * LDA + kq + lcol8);
            }
            #pragma unroll
            for (int g = 0; g < 4; g++) {
                uint32_t bh[2][2], bl[2][2], r0, r1, r2, r3;
                ldsm_x4(r0, r1, r2, r3, sBh + (wn + g*16 + lrow) * LDA + kq + lcol8);
                bh[0][0]=r0; bh[1][0]=r1; bh[0][1]=r2; bh[1][1]=r3;
                ldsm_x4(r0, r1, r2, r3, sBl + (wn + g*16 + lrow) * LDA + kq + lcol8);
                bl[0][0]=r0; bl[1][0]=r1; bl[0][1]=r2; bl[1][1]=r3;
                #pragma unroll
                for (int mt = 0; mt < 2; mt++)
                    #pragma unroll
                    for (int nn = 0; nn < 2; nn++) {
                        mma_bf16(D[mt][g*2+nn], ah[mt], bh[nn]);
                        mma_bf16(D[mt][g*2+nn], al[mt], bh[nn]);
                        mma_bf16(D[mt][g*2+nn], ah[mt], bl[nn]);
                    }
            }
        }

        // ---- C += zi[b, p] * D  (fp32, exact)
        #pragma unroll
        for (int mt = 0; mt < 2; mt++) {
            float z0 = szi[(wm + mt*16 + (lane >> 2))     * 17 + pi];
            float z1 = szi[(wm + mt*16 + (lane >> 2) + 8) * 17 + pi];
            #pragma unroll
            for (int nt = 0; nt < 8; nt++) {
                accC[mt][nt][0] += z0 * D[mt][nt][0];
                accC[mt][nt][1] += z0 * D[mt][nt][1];
                accC[mt][nt][2] += z1 * D[mt][nt][2];
                accC[mt][nt][3] += z1 * D[mt][nt][3];
            }
        }
        __syncthreads();
    }

    // ---- write partial tile
    float* dst = &g_part[chunk][0];
    #pragma unroll
    for (int mt = 0; mt < 2; mt++) {
        int row0 = m0 + wm + mt * 16 + (lane >> 2);
        #pragma unroll
        for (int nt = 0; nt < 8; nt++) {
            int col = wn + nt * 8 + (lane & 3) * 2;
            *(float2*)&dst[(size_t)row0 * HH + col] =
                make_float2(accC[mt][nt][0], accC[mt][nt][1]);
            *(float2*)&dst[(size_t)(row0 + 8) * HH + col] =
                make_float2(accC[mt][nt][2], accC[mt][nt][3]);
        }
    }
}

// ---------------- zero Y ------------------------------------------------------
__global__ void zero_y_kernel() {
    int i = blockIdx.x * blockDim.x + threadIdx.x;
    if (i < BB * HH) g_Y[i] = 0.f;
}

// ---------------- combine partials + BatchNorm + Y accumulate ----------------
__global__ __launch_bounds__(256) void bn_rank_kernel(
    const float* __restrict__ g, const float* __restrict__ bet)
{
    __shared__ float red[256];
    const int k = blockIdx.x;
    const int t = threadIdx.x;

    float xv[8];
    float s = 0.f;
    #pragma unroll
    for (int j = 0; j < 8; j++) {
        int b = j * 256 + t;
        float x = 0.f;
        #pragma unroll
        for (int c = 0; c < CHUNKS; c++)
            x += g_part[c][b*HH + k];
        xv[j] = x;
        s += x;
    }
    red[t] = s; __syncthreads();
    for (int o = 128; o > 0; o >>= 1) { if (t < o) red[t] += red[t + o]; __syncthreads(); }
    float mean = red[0] * (1.f / BB);
    __syncthreads();

    float s2 = 0.f;
    #pragma unroll
    for (int j = 0; j < 8; j++) { float d = xv[j] - mean; s2 += d * d; }
    red[t] = s2; __syncthreads();
    for (int o = 128; o > 0; o >>= 1) { if (t < o) red[t] += red[t + o]; __syncthreads(); }
    float var = red[0] * (1.f / BB);

    float inv = rsqrtf(var + 1e-5f);
    float gk = g[k], bk = bet[k];
    #pragma unroll
    for (int j = 0; j < 8; j++) {
        int b = j * 256 + t;
        float z = (xv[j] - mean) * inv * gk + bk;
        g_Zi[b*HH + k] = z;
        g_Y [b*HH + k] += z * (1.f / RANKN);
    }
}

// ---------------- BatchNorm on Y (in place) ----------------------------------
__global__ __launch_bounds__(256) void bn_final_kernel(
    const float* __restrict__ g, const float* __restrict__ bet)
{
    __shared__ float red[256];
    const int k = blockIdx.x;
    const int t = threadIdx.x;

    float xv[8];
    float s = 0.f;
    #pragma unroll
    for (int j = 0; j < 8; j++) {
        int b = j * 256 + t;
        float x = g_Y[b*HH + k];
        xv[j] = x;
        s += x;
    }
    red[t] = s; __syncthreads();
    for (int o = 128; o > 0; o >>= 1) { if (t < o) red[t] += red[t + o]; __syncthreads(); }
    float mean = red[0] * (1.f / BB);
    __syncthreads();

    float s2 = 0.f;
    #pragma unroll
    for (int j = 0; j < 8; j++) { float d = xv[j] - mean; s2 += d * d; }
    red[t] = s2; __syncthreads();
    for (int o = 128; o > 0; o >>= 1) { if (t < o) red[t] += red[t + o]; __syncthreads(); }
    float var = red[0] * (1.f / BB);

    float inv = rsqrtf(var + 1e-5f);
    float gk = g[k], bk = bet[k];
    #pragma unroll
    for (int j = 0; j < 8; j++) {
        int b = j * 256 + t;
        g_Y[b*HH + k] = (xv[j] - mean) * inv * gk + bk;
    }
}

// ---------------- launch ------------------------------------------------------
extern "C" void kernel_launch(void* const* d_in, const int* in_sizes, int n_in,
                              void* d_out, int out_size)
{
    const float* X  = (const float*)d_in[0];
    const float* W1 = (const float*)d_in[1];
    const float* b1 = (const float*)d_in[2];
    const float* W2 = (const float*)d_in[3];
    const float* b2 = (const float*)d_in[4];
    const float* W3 = (const float*)d_in[5];
    const float* b3 = (const float*)d_in[6];
    const float* P  = (const float*)d_in[7];
    const float* gz = (const float*)d_in[8];
    const float* bz = (const float*)d_in[9];
    const float* gy = (const float*)d_in[10];
    const float* by = (const float*)d_in[11];
    float* out = (float*)d_out;

    float *Zp, *Zip, *Yp, *R2p;
    __nv_bfloat16 *Zhp, *Zlp;
    cudaGetSymbolAddress((void**)&Zp,  g_Z);
    cudaGetSymbolAddress((void**)&Zip, g_Zi);
    cudaGetSymbolAddress((void**)&Yp,  g_Y);
    cudaGetSymbolAddress((void**)&R2p, g_R2);
    cudaGetSymbolAddress((void**)&Zhp, g_Zh);
    cudaGetSymbolAddress((void**)&Zlp, g_Zl);

    cudaFuncSetAttribute(quad_mma_kernel, cudaFuncAttributeMaxDynamicSharedMemorySize, SM_QTOT);

    // P pre-split + transpose (independent of everything else)
    prep_P_kernel<<<RANKN * HH, 256>>>(P);

    // Z = relu(X@W1 + b1) with bf16 hi/lo split; R2 = relu(X@W2 + b2)
    gemm_relu_kernel<<<64, 256>>>(X, W1, b1, nullptr, Zp,  INN, Zhp, Zlp);
    gemm_relu_kernel<<<64, 256>>>(X, W2, b2, nullptr, R2p, INN, nullptr, nullptr);
    zero_y_kernel<<<(BB*HH + 255)/256, 256>>>();

    // serial recurrence: tensor-core quad (parallel within rank) + BN per rank
    for (int r = 0; r < RANKN; r++) {
        const float* ziIn = (r == 0) ? Zp : Zip;
        quad_mma_kernel<<<dim3(BB/128, CHUNKS), 256, SM_QTOT>>>(ziIn, r);
        bn_rank_kernel<<<HH, 256>>>(gz, bz);
    }

    bn_final_kernel<<<HH, 256>>>(gy, by);

    // out = relu(relu(Y@W3 + b3) + R2)
    gemm_relu_kernel<<<64, 256>>>(Yp, W3, b3, R2p, out, HH, nullptr, nullptr);
}

// round 13
// speedup vs baseline: 3.0462x; 1.3677x over previous
#include <cuda_runtime.h>
#include <cuda_fp16.h>
#include <cstdint>

#define BB   2048
#define INN  256
#define HH   128
#define RANKN 8
#define CHUNKS 8
#define PPC   16         // p-values per chunk (CHUNKS*PPC = 128)

// ---------------- scratch (device globals) -----------------------------------
__device__ float g_Z [BB*HH];
__device__ float g_Zi[BB*HH];
__device__ float g_Y [BB*HH];
__device__ float g_R2[BB*HH];
__device__ __half g_Zh[BB*HH];
__device__ __half g_Zl[BB*HH];
__device__ __half g_Pt[(size_t)RANKN*HH*HH*HH];           // [r][p][k][q] fp16
__device__ float g_part[CHUNKS][BB*HH];                   // 8.4 MB partials

// ---------------- helpers -----------------------------------------------------
__device__ __forceinline__ uint32_t smem_u32(const void* p) {
    uint32_t a;
    asm("{ .reg .u64 t; cvta.to.shared.u64 t, %1; cvt.u32.u64 %0, t; }" : "=r"(a) : "l"(p));
    return a;
}
__device__ __forceinline__ void ldsm_x4(uint32_t& r0, uint32_t& r1, uint32_t& r2,
                                        uint32_t& r3, const void* p) {
    uint32_t a = smem_u32(p);
    asm volatile("ldmatrix.sync.aligned.m8n8.x4.shared.b16 {%0,%1,%2,%3}, [%4];"
                 : "=r"(r0), "=r"(r1), "=r"(r2), "=r"(r3) : "r"(a));
}
__device__ __forceinline__ void mma_f16(float* c, const uint32_t* a, const uint32_t* b) {
    asm volatile("mma.sync.aligned.m16n8k16.row.col.f32.f16.f16.f32 "
                 "{%0,%1,%2,%3}, {%4,%5,%6,%7}, {%8,%9}, {%0,%1,%2,%3};"
                 : "+f"(c[0]), "+f"(c[1]), "+f"(c[2]), "+f"(c[3])
                 : "r"(a[0]), "r"(a[1]), "r"(a[2]), "r"(a[3]), "r"(b[0]), "r"(b[1]));
}
__device__ __forceinline__ void cp16(uint32_t saddr, const void* g) {
    asm volatile("cp.async.cg.shared.global [%0], [%1], 16;" :: "r"(saddr), "l"(g));
}
__device__ __forceinline__ void cp_commit() { asm volatile("cp.async.commit_group;"); }
template<int N> __device__ __forceinline__ void cp_wait() {
    asm volatile("cp.async.wait_group %0;" :: "n"(N));
}

// ---------------- P fp16 + transpose ------------------------------------------
// out[r][p][k][q] fp16 from P[r][p][q][k] fp32
__global__ __launch_bounds__(256) void prep_P_kernel(const float* __restrict__ P) {
    __shared__ float tile[128 * 129];
    const int t  = threadIdx.x;
    const int rp = blockIdx.x;
    const float* src = P + (size_t)rp * 16384;
    for (int i = 0; i < 64; i++) {
        int idx = t + i * 256;                 // q*128 + k
        tile[(idx >> 7) * 129 + (idx & 127)] = src[idx];
    }
    __syncthreads();
    __half2* dh = (__half2*)(g_Pt + (size_t)rp * 16384);
    for (int i = 0; i < 32; i++) {
        int pi = t + i * 256;
        int o = pi * 2;
        int k = o >> 7, q = o & 127;
        float v0 = tile[q * 129 + k];
        float v1 = tile[(q + 1) * 129 + k];
        dh[pi] = __floats2half2_rn(v0, v1);
    }
}

// ---------------- GEMM + bias + relu (+ optional addon, + optional split) ----
__global__ __launch_bounds__(256) void gemm_relu_kernel(
    const float* __restrict__ X, const float* __restrict__ W,
    const float* __restrict__ bias, const float* __restrict__ addon,
    float* __restrict__ out, int K,
    __half* __restrict__ oh, __half* __restrict__ ol)
{
    __shared__ float sXt[32*32];
    __shared__ float sW [32*128];
    const int t  = threadIdx.x;
    const int tx = t & 31;
    const int ty = t >> 5;
    const int b0 = blockIdx.x * 32;

    float C[4][4] = {};
    for (int k0 = 0; k0 < K; k0 += 32) {
        {
            int b  = t >> 3;
            int kq = t & 7;
            float4 v = *(const float4*)&X[(b0 + b) * K + k0 + kq * 4];
            sXt[(kq*4+0)*32 + b] = v.x;
            sXt[(kq*4+1)*32 + b] = v.y;
            sXt[(kq*4+2)*32 + b] = v.z;
            sXt[(kq*4+3)*32 + b] = v.w;
        }
        #pragma unroll
        for (int w = 0; w < 4; w++) {
            int idx4 = t + 256 * w;
            int kk = idx4 >> 5, c4 = idx4 & 31;
            *(float4*)&sW[kk*128 + c4*4] = *(const float4*)&W[(k0 + kk) * 128 + c4 * 4];
        }
        __syncthreads();
        #pragma unroll
        for (int kk = 0; kk < 32; kk++) {
            float4 a4 = *(const float4*)&sXt[kk*32 + ty*4];
            float4 w4 = *(const float4*)&sW [kk*128 + tx*4];
            float av[4] = {a4.x, a4.y, a4.z, a4.w};
            float wv[4] = {w4.x, w4.y, w4.z, w4.w};
            #pragma unroll
            for (int i = 0; i < 4; i++)
                #pragma unroll
                for (int j = 0; j < 4; j++)
                    C[i][j] += av[i] * wv[j];
        }
        __syncthreads();
    }

    const int c = tx * 4;
    float bv[4];
    #pragma unroll
    for (int j = 0; j < 4; j++) bv[j] = bias[c + j];

    #pragma unroll
    for (int i = 0; i < 4; i++) {
        int b = b0 + ty * 4 + i;
        float r[4];
        #pragma unroll
        for (int j = 0; j < 4; j++) {
            float v = C[i][j] + bv[j];
            v = v > 0.f ? v : 0.f;
            if (addon) {
                v = v + addon[b * 128 + c + j];
                v = v > 0.f ? v : 0.f;
            }
            r[j] = v;
        }
        *(float4*)&out[b * 128 + c] = make_float4(r[0], r[1], r[2], r[3]);
        if (oh) {
            __half h[4], l[4];
            #pragma unroll
            for (int j = 0; j < 4; j++) {
                h[j] = __float2half_rn(r[j]);
                l[j] = __float2half_rn(r[j] - __half2float(h[j]));
            }
            *(__half2*)&oh[b*128 + c]     = __halves2half2(h[0], h[1]);
            *(__half2*)&oh[b*128 + c + 2] = __halves2half2(h[2], h[3]);
            *(__half2*)&ol[b*128 + c]     = __halves2half2(l[0], l[1]);
            *(__half2*)&ol[b*128 + c + 2] = __halves2half2(l[2], l[3]);
        }
    }
}

// ---------------- quadratic rank kernel v3 (fp16 2-product) ------------------
// For each p: D = Zh @ P_p + Zl @ P_p = Z @ P_p (P fp16-rounded), then
// C += zi[b,p] * D (fp32 register epilogue). B 3-stage cp.async pipeline.
// grid (16 M-tiles, 8 chunks), 256 threads = 8 warps (32x64 tiles).
#define LDA    136                      // padded fp16 row stride
#define ABYTES (128*LDA*2)              // 34816 per 128x128 fp16 tile
#define O_AH   0
#define O_AL   ABYTES
#define O_B0   (2*ABYTES)
#define O_ZI   (5*ABYTES)               // after 3 B stages
#define SM_QTOT (O_ZI + 128*17*4)       // 182784

__global__ __launch_bounds__(256) void quad_mma_kernel(
    const float* __restrict__ zi_in, int r)
{
    extern __shared__ char smem[];
    const uint32_t sb = smem_u32(smem);
    const int t     = threadIdx.x;
    const int w     = t >> 5;
    const int lane  = t & 31;
    const int m0    = blockIdx.x * 128;
    const int chunk = blockIdx.y;
    const int wm    = (w >> 1) * 32;
    const int wn    = (w & 1) * 64;
    const int p0    = chunk * PPC;

    const int lrow  = ((lane >> 3) & 1) * 8 + (lane & 7);
    const int lcol8 = ((lane >> 4) & 1) * 8;

    __half* sAh = (__half*)(smem + O_AH);
    __half* sAl = (__half*)(smem + O_AL);
    float*  szi = (float*)(smem + O_ZI);

    // ---- stage A = Z hi/lo tiles + B tile for p0 (group 0)
    {
        const char* gh = (const char*)(g_Zh + (size_t)m0 * HH);
        const char* gl = (const char*)(g_Zl + (size_t)m0 * HH);
        const char* gb = (const char*)(g_Pt + ((size_t)r * HH + p0) * 16384);
        #pragma unroll
        for (int pass = 0; pass < 8; pass++) {
            int idx = t + pass * 256;           // 16B unit, 16 per row
            uint32_t off = (uint32_t)(idx >> 4) * (LDA*2) + (uint32_t)(idx & 15) * 16;
            cp16(sb + O_AH + off, gh + (size_t)idx * 16);
            cp16(sb + O_AL + off, gl + (size_t)idx * 16);
            cp16(sb + O_B0 + off, gb + (size_t)idx * 16);
        }
    }
    cp_commit();
    // ---- B tile for p0+1 (group 1)
    {
        const char* gb = (const char*)(g_Pt + ((size_t)r * HH + p0 + 1) * 16384);
        #pragma unroll
        for (int pass = 0; pass < 8; pass++) {
            int idx = t + pass * 256;
            uint32_t off = (uint32_t)(idx >> 4) * (LDA*2) + (uint32_t)(idx & 15) * 16;
            cp16(sb + O_B0 + ABYTES + off, gb + (size_t)idx * 16);
        }
    }
    cp_commit();

    // ---- stage zi chunk [128 rows][16 p] (plain loads)
    {
        int row = t >> 1, h = (t & 1) * 8;
        const float* zp = zi_in + (size_t)(m0 + row) * HH + p0 + h;
        float4 v0 = *(const float4*)(zp);
        float4 v1 = *(const float4*)(zp + 4);
        float* d = szi + row * 17 + h;
        d[0]=v0.x; d[1]=v0.y; d[2]=v0.z; d[3]=v0.w;
        d[4]=v1.x; d[5]=v1.y; d[6]=v1.z; d[7]=v1.w;
    }

    float accC[2][8][4] = {};

    for (int pi = 0; pi < PPC; pi++) {
        // prefetch B for pi+2 into stage (pi+2)%3, then wait for stage pi%3
        if (pi + 2 < PPC) {
            const char* gb = (const char*)(g_Pt + ((size_t)r * HH + p0 + pi + 2) * 16384);
            const uint32_t base = sb + O_B0 + (uint32_t)((pi + 2) % 3) * ABYTES;
            #pragma unroll
            for (int pass = 0; pass < 8; pass++) {
                int idx = t + pass * 256;
                uint32_t off = (uint32_t)(idx >> 4) * (LDA*2) + (uint32_t)(idx & 15) * 16;
                cp16(base + off, gb + (size_t)idx * 16);
            }
            cp_commit();
            cp_wait<2>();
        } else if (pi + 2 == PPC) {
            cp_wait<1>();
        } else {
            cp_wait<0>();
        }
        __syncthreads();

        __half* sBh = (__half*)(smem + O_B0 + (size_t)(pi % 3) * ABYTES);

        float D[2][8][4] = {};

        #pragma unroll
        for (int ks = 0; ks < 8; ks++) {
            const int kq = ks * 16;
            uint32_t ah[2][4], al[2][4];
            #pragma unroll
            for (int mt = 0; mt < 2; mt++) {
                ldsm_x4(ah[mt][0], ah[mt][1], ah[mt][2], ah[mt][3],
                        sAh + (wm + mt*16 + lrow) * LDA + kq + lcol8);
                ldsm_x4(al[mt][0], al[mt][1], al[mt][2], al[mt][3],
                        sAl + (wm + mt*16 + lrow) * LDA + kq + lcol8);
            }
            #pragma unroll
            for (int g = 0; g < 4; g++) {
                uint32_t bh[2][2], r0, r1, r2, r3;
                ldsm_x4(r0, r1, r2, r3, sBh + (wn + g*16 + lrow) * LDA + kq + lcol8);
                bh[0][0]=r0; bh[1][0]=r1; bh[0][1]=r2; bh[1][1]=r3;
                #pragma unroll
                for (int mt = 0; mt < 2; mt++)
                    #pragma unroll
                    for (int nn = 0; nn < 2; nn++) {
                        mma_f16(D[mt][g*2+nn], ah[mt], bh[nn]);
                        mma_f16(D[mt][g*2+nn], al[mt], bh[nn]);
                    }
            }
        }

        // ---- C += zi[b, p] * D  (fp32, exact)
        #pragma unroll
        for (int mt = 0; mt < 2; mt++) {
            float z0 = szi[(wm + mt*16 + (lane >> 2))     * 17 + pi];
            float z1 = szi[(wm + mt*16 + (lane >> 2) + 8) * 17 + pi];
            #pragma unroll
            for (int nt = 0; nt < 8; nt++) {
                accC[mt][nt][0] += z0 * D[mt][nt][0];
                accC[mt][nt][1] += z0 * D[mt][nt][1];
                accC[mt][nt][2] += z1 * D[mt][nt][2];
                accC[mt][nt][3] += z1 * D[mt][nt][3];
            }
        }
    }

    // ---- write partial tile
    float* dst = &g_part[chunk][0];
    #pragma unroll
    for (int mt = 0; mt < 2; mt++) {
        int row0 = m0 + wm + mt * 16 + (lane >> 2);
        #pragma unroll
        for (int nt = 0; nt < 8; nt++) {
            int col = wn + nt * 8 + (lane & 3) * 2;
            *(float2*)&dst[(size_t)row0 * HH + col] =
                make_float2(accC[mt][nt][0], accC[mt][nt][1]);
            *(float2*)&dst[(size_t)(row0 + 8) * HH + col] =
                make_float2(accC[mt][nt][2], accC[mt][nt][3]);
        }
    }
}

// ---------------- combine partials + BatchNorm + Y accumulate ----------------
__global__ __launch_bounds__(256) void bn_rank_kernel(
    const float* __restrict__ g, const float* __restrict__ bet, int first)
{
    __shared__ float red[256];
    const int k = blockIdx.x;
    const int t = threadIdx.x;

    float xv[8];
    float s = 0.f;
    #pragma unroll
    for (int j = 0; j < 8; j++) {
        int b = j * 256 + t;
        float x = 0.f;
        #pragma unroll
        for (int c = 0; c < CHUNKS; c++)
            x += g_part[c][b*HH + k];
        xv[j] = x;
        s += x;
    }
    red[t] = s; __syncthreads();
    for (int o = 128; o > 0; o >>= 1) { if (t < o) red[t] += red[t + o]; __syncthreads(); }
    float mean = red[0] * (1.f / BB);
    __syncthreads();

    float s2 = 0.f;
    #pragma unroll
    for (int j = 0; j < 8; j++) { float d = xv[j] - mean; s2 += d * d; }
    red[t] = s2; __syncthreads();
    for (int o = 128; o > 0; o >>= 1) { if (t < o) red[t] += red[t + o]; __syncthreads(); }
    float var = red[0] * (1.f / BB);

    float inv = rsqrtf(var + 1e-5f);
    float gk = g[k], bk = bet[k];
    #pragma unroll
    for (int j = 0; j < 8; j++) {
        int b = j * 256 + t;
        float z = (xv[j] - mean) * inv * gk + bk;
        g_Zi[b*HH + k] = z;
        if (first) g_Y[b*HH + k] = z * (1.f / RANKN);
        else       g_Y[b*HH + k] += z * (1.f / RANKN);
    }
}

// ---------------- BatchNorm on Y (in place) ----------------------------------
__global__ __launch_bounds__(256) void bn_final_kernel(
    const float* __restrict__ g, const float* __restrict__ bet)
{
    __shared__ float red[256];
    const int k = blockIdx.x;
    const int t = threadIdx.x;

    float xv[8];
    float s = 0.f;
    #pragma unroll
    for (int j = 0; j < 8; j++) {
        int b = j * 256 + t;
        float x = g_Y[b*HH + k];
        xv[j] = x;
        s += x;
    }
    red[t] = s; __syncthreads();
    for (int o = 128; o > 0; o >>= 1) { if (t < o) red[t] += red[t + o]; __syncthreads(); }
    float mean = red[0] * (1.f / BB);
    __syncthreads();

    float s2 = 0.f;
    #pragma unroll
    for (int j = 0; j < 8; j++) { float d = xv[j] - mean; s2 += d * d; }
    red[t] = s2; __syncthreads();
    for (int o = 128; o > 0; o >>= 1) { if (t < o) red[t] += red[t + o]; __syncthreads(); }
    float var = red[0] * (1.f / BB);

    float inv = rsqrtf(var + 1e-5f);
    float gk = g[k], bk = bet[k];
    #pragma unroll
    for (int j = 0; j < 8; j++) {
        int b = j * 256 + t;
        g_Y[b*HH + k] = (xv[j] - mean) * inv * gk + bk;
    }
}

// ---------------- launch ------------------------------------------------------
extern "C" void kernel_launch(void* const* d_in, const int* in_sizes, int n_in,
                              void* d_out, int out_size)
{
    const float* X  = (const float*)d_in[0];
    const float* W1 = (const float*)d_in[1];
    const float* b1 = (const float*)d_in[2];
    const float* W2 = (const float*)d_in[3];
    const float* b2 = (const float*)d_in[4];
    const float* W3 = (const float*)d_in[5];
    const float* b3 = (const float*)d_in[6];
    const float* P  = (const float*)d_in[7];
    const float* gz = (const float*)d_in[8];
    const float* bz = (const float*)d_in[9];
    const float* gy = (const float*)d_in[10];
    const float* by = (const float*)d_in[11];
    float* out = (float*)d_out;

    float *Zp, *Zip, *Yp, *R2p;
    __half *Zhp, *Zlp;
    cudaGetSymbolAddress((void**)&Zp,  g_Z);
    cudaGetSymbolAddress((void**)&Zip, g_Zi);
    cudaGetSymbolAddress((void**)&Yp,  g_Y);
    cudaGetSymbolAddress((void**)&R2p, g_R2);
    cudaGetSymbolAddress((void**)&Zhp, g_Zh);
    cudaGetSymbolAddress((void**)&Zlp, g_Zl);

    cudaFuncSetAttribute(quad_mma_kernel, cudaFuncAttributeMaxDynamicSharedMemorySize, SM_QTOT);

    // P fp16 + transpose (independent of everything else)
    prep_P_kernel<<<RANKN * HH, 256>>>(P);

    // Z = relu(X@W1 + b1) with fp16 hi/lo split; R2 = relu(X@W2 + b2)
    gemm_relu_kernel<<<64, 256>>>(X, W1, b1, nullptr, Zp,  INN, Zhp, Zlp);
    gemm_relu_kernel<<<64, 256>>>(X, W2, b2, nullptr, R2p, INN, nullptr, nullptr);

    // serial recurrence: tensor-core quad (parallel within rank) + BN per rank
    for (int r = 0; r < RANKN; r++) {
        const float* ziIn = (r == 0) ? Zp : Zip;
        quad_mma_kernel<<<dim3(BB/128, CHUNKS), 256, SM_QTOT>>>(ziIn, r);
        bn_rank_kernel<<<HH, 256>>>(gz, bz, r == 0);
    }

    bn_final_kernel<<<HH, 256>>>(gy, by);

    // out = relu(relu(Y@W3 + b3) + R2)
    gemm_relu_kernel<<<64, 256>>>(Yp, W3, b3, R2p, out, HH, nullptr, nullptr);
}

// round 17
// speedup vs baseline: 4.3914x; 1.4416x over previous
#include <cuda_runtime.h>
#include <cuda_fp16.h>
#include <cstdint>

#define BB   2048
#define INN  256
#define HH   128
#define RANKN 8
#define CHUNKS 8
#define PPC   16         // p-values per chunk (CHUNKS*PPC = 128)

// ---------------- scratch (device globals) -----------------------------------
__device__ float g_Z [BB*HH];
__device__ float g_Zi[BB*HH];
__device__ float g_Y [BB*HH];
__device__ float g_R2[BB*HH];
__device__ __half g_Zh[BB*HH];
__device__ __half g_Pt[(size_t)RANKN*HH*HH*HH];           // [r][p][k][q] fp16
__device__ float g_part[CHUNKS][BB*HH];                   // 8.4 MB partials

// ---------------- helpers -----------------------------------------------------
__device__ __forceinline__ uint32_t smem_u32(const void* p) {
    uint32_t a;
    asm("{ .reg .u64 t; cvta.to.shared.u64 t, %1; cvt.u32.u64 %0, t; }" : "=r"(a) : "l"(p));
    return a;
}
__device__ __forceinline__ void ldsm_x4(uint32_t& r0, uint32_t& r1, uint32_t& r2,
                                        uint32_t& r3, const void* p) {
    uint32_t a = smem_u32(p);
    asm volatile("ldmatrix.sync.aligned.m8n8.x4.shared.b16 {%0,%1,%2,%3}, [%4];"
                 : "=r"(r0), "=r"(r1), "=r"(r2), "=r"(r3) : "r"(a));
}
__device__ __forceinline__ void mma_f16(float* c, const uint32_t* a, const uint32_t* b) {
    asm volatile("mma.sync.aligned.m16n8k16.row.col.f32.f16.f16.f32 "
                 "{%0,%1,%2,%3}, {%4,%5,%6,%7}, {%8,%9}, {%0,%1,%2,%3};"
                 : "+f"(c[0]), "+f"(c[1]), "+f"(c[2]), "+f"(c[3])
                 : "r"(a[0]), "r"(a[1]), "r"(a[2]), "r"(a[3]), "r"(b[0]), "r"(b[1]));
}
__device__ __forceinline__ void cp16(uint32_t saddr, const void* g) {
    asm volatile("cp.async.cg.shared.global [%0], [%1], 16;" :: "r"(saddr), "l"(g));
}
__device__ __forceinline__ void cp_commit() { asm volatile("cp.async.commit_group;"); }
template<int N> __device__ __forceinline__ void cp_wait() {
    asm volatile("cp.async.wait_group %0;" :: "n"(N));
}

// ---------------- P fp16 + transpose ------------------------------------------
// out[r][p][k][q] fp16 from P[r][p][q][k] fp32
__global__ __launch_bounds__(256) void prep_P_kernel(const float* __restrict__ P) {
    __shared__ float tile[128 * 129];
    const int t  = threadIdx.x;
    const int rp = blockIdx.x;
    const float* src = P + (size_t)rp * 16384;
    for (int i = 0; i < 64; i++) {
        int idx = t + i * 256;                 // q*128 + k
        tile[(idx >> 7) * 129 + (idx & 127)] = src[idx];
    }
    __syncthreads();
    __half2* dh = (__half2*)(g_Pt + (size_t)rp * 16384);
    for (int i = 0; i < 32; i++) {
        int pi = t + i * 256;
        int o = pi * 2;
        int k = o >> 7, q = o & 127;
        float v0 = tile[q * 129 + k];
        float v1 = tile[(q + 1) * 129 + k];
        dh[pi] = __floats2half2_rn(v0, v1);
    }
}

// ---------------- GEMM + bias + relu (+ optional addon, + optional fp16 out) -
__global__ __launch_bounds__(256) void gemm_relu_kernel(
    const float* __restrict__ X, const float* __restrict__ W,
    const float* __restrict__ bias, const float* __restrict__ addon,
    float* __restrict__ out, int K,
    __half* __restrict__ oh)
{
    __shared__ float sXt[32*32];
    __shared__ float sW [32*128];
    const int t  = threadIdx.x;
    const int tx = t & 31;
    const int ty = t >> 5;
    const int b0 = blockIdx.x * 32;

    float C[4][4] = {};
    for (int k0 = 0; k0 < K; k0 += 32) {
        {
            int b  = t >> 3;
            int kq = t & 7;
            float4 v = *(const float4*)&X[(b0 + b) * K + k0 + kq * 4];
            sXt[(kq*4+0)*32 + b] = v.x;
            sXt[(kq*4+1)*32 + b] = v.y;
            sXt[(kq*4+2)*32 + b] = v.z;
            sXt[(kq*4+3)*32 + b] = v.w;
        }
        #pragma unroll
        for (int w = 0; w < 4; w++) {
            int idx4 = t + 256 * w;
            int kk = idx4 >> 5, c4 = idx4 & 31;
            *(float4*)&sW[kk*128 + c4*4] = *(const float4*)&W[(k0 + kk) * 128 + c4 * 4];
        }
        __syncthreads();
        #pragma unroll
        for (int kk = 0; kk < 32; kk++) {
            float4 a4 = *(const float4*)&sXt[kk*32 + ty*4];
            float4 w4 = *(const float4*)&sW [kk*128 + tx*4];
            float av[4] = {a4.x, a4.y, a4.z, a4.w};
            float wv[4] = {w4.x, w4.y, w4.z, w4.w};
            #pragma unroll
            for (int i = 0; i < 4; i++)
                #pragma unroll
                for (int j = 0; j < 4; j++)
                    C[i][j] += av[i] * wv[j];
        }
        __syncthreads();
    }

    const int c = tx * 4;
    float bv[4];
    #pragma unroll
    for (int j = 0; j < 4; j++) bv[j] = bias[c + j];

    #pragma unroll
    for (int i = 0; i < 4; i++) {
        int b = b0 + ty * 4 + i;
        float r[4];
        #pragma unroll
        for (int j = 0; j < 4; j++) {
            float v = C[i][j] + bv[j];
            v = v > 0.f ? v : 0.f;
            if (addon) {
                v = v + addon[b * 128 + c + j];
                v = v > 0.f ? v : 0.f;
            }
            r[j] = v;
        }
        *(float4*)&out[b * 128 + c] = make_float4(r[0], r[1], r[2], r[3]);
        if (oh) {
            *(__half2*)&oh[b*128 + c]     = __floats2half2_rn(r[0], r[1]);
            *(__half2*)&oh[b*128 + c + 2] = __floats2half2_rn(r[2], r[3]);
        }
    }
}

// ---------------- quadratic rank kernel v4 (fp16 1-product, A hoisted) -------
// For each p: D = Z @ P_p (fp16 tensor cores, fp32 accum), then
// C += zi[b,p] * D (fp32 register epilogue). A fragments live in registers
// for the whole kernel; B 3-stage cp.async pipeline.
// grid (16 M-tiles, 8 chunks), 256 threads = 8 warps (32x64 tiles).
#define LDA    136                      // padded fp16 row stride
#define ABYTES (128*LDA*2)              // 34816 per 128x128 fp16 tile
#define O_A    0
#define O_B0   ABYTES
#define O_ZI   (4*ABYTES)               // after 3 B stages
#define SM_QTOT (O_ZI + 128*17*4)       // 147968

__global__ __launch_bounds__(256, 1) void quad_mma_kernel(
    const float* __restrict__ zi_in, int r)
{
    extern __shared__ char smem[];
    const uint32_t sb = smem_u32(smem);
    const int t     = threadIdx.x;
    const int w     = t >> 5;
    const int lane  = t & 31;
    const int m0    = blockIdx.x * 128;
    const int chunk = blockIdx.y;
    const int wm    = (w >> 1) * 32;
    const int wn    = (w & 1) * 64;
    const int p0    = chunk * PPC;

    const int lrow  = ((lane >> 3) & 1) * 8 + (lane & 7);
    const int lcol8 = ((lane >> 4) & 1) * 8;

    __half* sA  = (__half*)(smem + O_A);
    float*  szi = (float*)(smem + O_ZI);

    // ---- group 0: A (Zh) tile + B tile for p0
    {
        const char* ga = (const char*)(g_Zh + (size_t)m0 * HH);
        const char* gb = (const char*)(g_Pt + ((size_t)r * HH + p0) * 16384);
        #pragma unroll
        for (int pass = 0; pass < 8; pass++) {
            int idx = t + pass * 256;           // 16B unit, 16 per row
            uint32_t off = (uint32_t)(idx >> 4) * (LDA*2) + (uint32_t)(idx & 15) * 16;
            cp16(sb + O_A + off,  ga + (size_t)idx * 16);
            cp16(sb + O_B0 + off, gb + (size_t)idx * 16);
        }
    }
    cp_commit();
    // ---- group 1: B tile for p0+1
    {
        const char* gb = (const char*)(g_Pt + ((size_t)r * HH + p0 + 1) * 16384);
        #pragma unroll
        for (int pass = 0; pass < 8; pass++) {
            int idx = t + pass * 256;
            uint32_t off = (uint32_t)(idx >> 4) * (LDA*2) + (uint32_t)(idx & 15) * 16;
            cp16(sb + O_B0 + ABYTES + off, gb + (size_t)idx * 16);
        }
    }
    cp_commit();

    // ---- stage zi chunk [128 rows][16 p]
    {
        int row = t >> 1, h = (t & 1) * 8;
        const float* zp = zi_in + (size_t)(m0 + row) * HH + p0 + h;
        float4 v0 = *(const float4*)(zp);
        float4 v1 = *(const float4*)(zp + 4);
        float* d = szi + row * 17 + h;
        d[0]=v0.x; d[1]=v0.y; d[2]=v0.z; d[3]=v0.w;
        d[4]=v1.x; d[5]=v1.y; d[6]=v1.z; d[7]=v1.w;
    }

    // ---- A ready -> hoist ALL A fragments into registers (constant over pi)
    cp_wait<1>();
    __syncthreads();
    uint32_t ah[8][2][4];
    #pragma unroll
    for (int ks = 0; ks < 8; ks++)
        #pragma unroll
        for (int mt = 0; mt < 2; mt++)
            ldsm_x4(ah[ks][mt][0], ah[ks][mt][1], ah[ks][mt][2], ah[ks][mt][3],
                    sA + (wm + mt*16 + lrow) * LDA + ks*16 + lcol8);

    float accC[2][8][4] = {};

    for (int pi = 0; pi < PPC; pi++) {
        // prefetch B for pi+2 into stage (pi+2)%3, then ensure B(pi) ready
        if (pi + 2 < PPC) {
            const char* gb = (const char*)(g_Pt + ((size_t)r * HH + p0 + pi + 2) * 16384);
            const uint32_t base = sb + O_B0 + (uint32_t)((pi + 2) % 3) * ABYTES;
            #pragma unroll
            for (int pass = 0; pass < 8; pass++) {
                int idx = t + pass * 256;
                uint32_t off = (uint32_t)(idx >> 4) * (LDA*2) + (uint32_t)(idx & 15) * 16;
                cp16(base + off, gb + (size_t)idx * 16);
            }
            cp_commit();
            cp_wait<2>();
        } else if (pi + 2 == PPC) {
            cp_wait<1>();
        } else {
            cp_wait<0>();
        }
        __syncthreads();

        __half* sBh = (__half*)(smem + O_B0 + (size_t)(pi % 3) * ABYTES);

        float D[2][8][4] = {};

        #pragma unroll
        for (int ks = 0; ks < 8; ks++) {
            const int kq = ks * 16;
            #pragma unroll
            for (int g = 0; g < 4; g++) {
                uint32_t bh[2][2], r0, r1, r2, r3;
                ldsm_x4(r0, r1, r2, r3, sBh + (wn + g*16 + lrow) * LDA + kq + lcol8);
                bh[0][0]=r0; bh[1][0]=r1; bh[0][1]=r2; bh[1][1]=r3;
                #pragma unroll
                for (int mt = 0; mt < 2; mt++)
                    #pragma unroll
                    for (int nn = 0; nn < 2; nn++)
                        mma_f16(D[mt][g*2+nn], ah[ks][mt], bh[nn]);
            }
        }

        // ---- C += zi[b, p] * D  (fp32, exact)
        #pragma unroll
        for (int mt = 0; mt < 2; mt++) {
            float z0 = szi[(wm + mt*16 + (lane >> 2))     * 17 + pi];
            float z1 = szi[(wm + mt*16 + (lane >> 2) + 8) * 17 + pi];
            #pragma unroll
            for (int nt = 0; nt < 8; nt++) {
                accC[mt][nt][0] += z0 * D[mt][nt][0];
                accC[mt][nt][1] += z0 * D[mt][nt][1];
                accC[mt][nt][2] += z1 * D[mt][nt][2];
                accC[mt][nt][3] += z1 * D[mt][nt][3];
            }
        }
    }

    // ---- write partial tile
    float* dst = &g_part[chunk][0];
    #pragma unroll
    for (int mt = 0; mt < 2; mt++) {
        int row0 = m0 + wm + mt * 16 + (lane >> 2);
        #pragma unroll
        for (int nt = 0; nt < 8; nt++) {
            int col = wn + nt * 8 + (lane & 3) * 2;
            *(float2*)&dst[(size_t)row0 * HH + col] =
                make_float2(accC[mt][nt][0], accC[mt][nt][1]);
            *(float2*)&dst[(size_t)(row0 + 8) * HH + col] =
                make_float2(accC[mt][nt][2], accC[mt][nt][3]);
        }
    }
}

// ---------------- combine partials + BatchNorm + Y accumulate ----------------
__global__ __launch_bounds__(256) void bn_rank_kernel(
    const float* __restrict__ g, const float* __restrict__ bet, int first)
{
    __shared__ float red[256];
    const int k = blockIdx.x;
    const int t = threadIdx.x;

    float xv[8];
    float s = 0.f;
    #pragma unroll
    for (int j = 0; j < 8; j++) {
        int b = j * 256 + t;
        float x = 0.f;
        #pragma unroll
        for (int c = 0; c < CHUNKS; c++)
            x += g_part[c][b*HH + k];
        xv[j] = x;
        s += x;
    }
    red[t] = s; __syncthreads();
    for (int o = 128; o > 0; o >>= 1) { if (t < o) red[t] += red[t + o]; __syncthreads(); }
    float mean = red[0] * (1.f / BB);
    __syncthreads();

    float s2 = 0.f;
    #pragma unroll
    for (int j = 0; j < 8; j++) { float d = xv[j] - mean; s2 += d * d; }
    red[t] = s2; __syncthreads();
    for (int o = 128; o > 0; o >>= 1) { if (t < o) red[t] += red[t + o]; __syncthreads(); }
    float var = red[0] * (1.f / BB);

    float inv = rsqrtf(var + 1e-5f);
    float gk = g[k], bk = bet[k];
    #pragma unroll
    for (int j = 0; j < 8; j++) {
        int b = j * 256 + t;
        float z = (xv[j] - mean) * inv * gk + bk;
        g_Zi[b*HH + k] = z;
        if (first) g_Y[b*HH + k] = z * (1.f / RANKN);
        else       g_Y[b*HH + k] += z * (1.f / RANKN);
    }
}

// ---------------- BatchNorm on Y (in place) ----------------------------------
__global__ __launch_bounds__(256) void bn_final_kernel(
    const float* __restrict__ g, const float* __restrict__ bet)
{
    __shared__ float red[256];
    const int k = blockIdx.x;
    const int t = threadIdx.x;

    float xv[8];
    float s = 0.f;
    #pragma unroll
    for (int j = 0; j < 8; j++) {
        int b = j * 256 + t;
        float x = g_Y[b*HH + k];
        xv[j] = x;
        s += x;
    }
    red[t] = s; __syncthreads();
    for (int o = 128; o > 0; o >>= 1) { if (t < o) red[t] += red[t + o]; __syncthreads(); }
    float mean = red[0] * (1.f / BB);
    __syncthreads();

    float s2 = 0.f;
    #pragma unroll
    for (int j = 0; j < 8; j++) { float d = xv[j] - mean; s2 += d * d; }
    red[t] = s2; __syncthreads();
    for (int o = 128; o > 0; o >>= 1) { if (t < o) red[t] += red[t + o]; __syncthreads(); }
    float var = red[0] * (1.f / BB);

    float inv = rsqrtf(var + 1e-5f);
    float gk = g[k], bk = bet[k];
    #pragma unroll
    for (int j = 0; j < 8; j++) {
        int b = j * 256 + t;
        g_Y[b*HH + k] = (xv[j] - mean) * inv * gk + bk;
    }
}

// ---------------- launch ------------------------------------------------------
extern "C" void kernel_launch(void* const* d_in, const int* in_sizes, int n_in,
                              void* d_out, int out_size)
{
    const float* X  = (const float*)d_in[0];
    const float* W1 = (const float*)d_in[1];
    const float* b1 = (const float*)d_in[2];
    const float* W2 = (const float*)d_in[3];
    const float* b2 = (const float*)d_in[4];
    const float* W3 = (const float*)d_in[5];
    const float* b3 = (const float*)d_in[6];
    const float* P  = (const float*)d_in[7];
    const float* gz = (const float*)d_in[8];
    const float* bz = (const float*)d_in[9];
    const float* gy = (const float*)d_in[10];
    const float* by = (const float*)d_in[11];
    float* out = (float*)d_out;

    float *Zp, *Zip, *Yp, *R2p;
    __half *Zhp;
    cudaGetSymbolAddress((void**)&Zp,  g_Z);
    cudaGetSymbolAddress((void**)&Zip, g_Zi);
    cudaGetSymbolAddress((void**)&Yp,  g_Y);
    cudaGetSymbolAddress((void**)&R2p, g_R2);
    cudaGetSymbolAddress((void**)&Zhp, g_Zh);

    cudaFuncSetAttribute(quad_mma_kernel, cudaFuncAttributeMaxDynamicSharedMemorySize, SM_QTOT);

    // P fp16 + transpose (independent of everything else)
    prep_P_kernel<<<RANKN * HH, 256>>>(P);

    // Z = relu(X@W1 + b1) with fp16 copy; R2 = relu(X@W2 + b2)
    gemm_relu_kernel<<<64, 256>>>(X, W1, b1, nullptr, Zp,  INN, Zhp);
    gemm_relu_kernel<<<64, 256>>>(X, W2, b2, nullptr, R2p, INN, nullptr);

    // serial recurrence: tensor-core quad (parallel within rank) + BN per rank
    for (int r = 0; r < RANKN; r++) {
        const float* ziIn = (r == 0) ? Zp : Zip;
        quad_mma_kernel<<<dim3(BB/128, CHUNKS), 256, SM_QTOT>>>(ziIn, r);
        bn_rank_kernel<<<HH, 256>>>(gz, bz, r == 0);
    }

    bn_final_kernel<<<HH, 256>>>(gy, by);

    // out = relu(relu(Y@W3 + b3) + R2)
    gemm_relu_kernel<<<64, 256>>>(Yp, W3, b3, R2p, out, HH, nullptr);
}